// round 1
// baseline (speedup 1.0000x reference)
#include <cuda_runtime.h>
#include <cstdint>

// Problem constants
#define BATCH 1024
#define TSTEPS 12
#define IDIM 1024
#define HDIM 1024
#define PDIM 1024
#define CDIM 512
#define TAU 0.25f

// ---------------- scratch (static device memory; no allocations) -------------
__device__ float g_U[(size_t)BATCH * TSTEPS * HDIM];          // x @ w_oh, [B*T, H] (row = b*12+t)
__device__ float g_ah[TSTEPS][(size_t)BATCH * HDIM];          // slot s holds a_h_{s-1}; slot0 = 0.5
__device__ float g_ap[2][(size_t)BATCH * PDIM];
__device__ float g_ps[2][(size_t)BATCH * PDIM];
__device__ float g_ac[2][(size_t)BATCH * CDIM];
__device__ float g_cs[2][(size_t)BATCH * CDIM];

// ---------------- init: carry0 -------------------------------------------------
__global__ void init_kernel() {
    int i = blockIdx.x * blockDim.x + threadIdx.x;
    if (i < BATCH * PDIM) {
        g_ah[0][i] = 0.5f;   // a_h_{-1}
        g_ap[0][i] = 0.5f;   // a_p_{-1}
        g_ps[0][i] = 0.0f;   // p_{-1}
    }
    if (i < BATCH * CDIM) {
        g_ac[0][i] = 0.5f;   // a_c_{-1}
        g_cs[0][i] = 0.0f;   // c_{-1}
    }
}

// ---------------- h-scan: linear leaky integration + sigmoid ------------------
// h_t = TAU*(U_t + bias_h) + 0.75*h_{t-1};  a_h_t = sigmoid(h_t) -> slot t+1
__global__ void hscan_kernel(const float* __restrict__ bias_h) {
    int i = blockIdx.x * blockDim.x + threadIdx.x;   // 0 .. B*H-1
    if (i >= BATCH * HDIM) return;
    int b = i >> 10;           // HDIM = 1024
    int h = i & 1023;
    float bh = bias_h[h];
    float hh = 0.0f;
    const float* Ub = g_U + (size_t)b * TSTEPS * HDIM + h;
#pragma unroll
    for (int t = 0; t < TSTEPS - 1; ++t) {          // a_h_11 never consumed
        hh = TAU * (Ub[(size_t)t * HDIM] + bh) + (1.0f - TAU) * hh;
        g_ah[t + 1][i] = 1.0f / (1.0f + expf(-hh));
    }
}

// ---------------- generic multi-segment SGEMM with fused epilogue -------------
#define BM 128
#define BN 128
#define BK 16

struct Seg { const float* A; const float* B; int K; };

struct GemmDesc {
    Seg seg[3];
    int nseg;
    int N;        // output columns (also ldb and ld of all outputs)
    int grid_n;   // N / BN
    const float* bias;
    const float* prev;
    float* state_out;
    float* act_out;
    float* extra_out;   // nullable (d_out slice)
    int mode;           // 0: store acc to state_out; 1: leaky blend + sigmoid
};

__global__ __launch_bounds__(256, 2)
void gemm_kernel(GemmDesc dA, GemmDesc dB, int nblocksA) {
    GemmDesc d;
    int bid;
    if ((int)blockIdx.x < nblocksA) { d = dA; bid = blockIdx.x; }
    else                            { d = dB; bid = blockIdx.x - nblocksA; }

    const int bm = bid / d.grid_n;
    const int bn = bid % d.grid_n;

    __shared__ float As[BK][BM + 4];
    __shared__ float Bs[BK][BN];

    const int tid = threadIdx.x;
    const int tx = tid & 15;      // 0..15 (cols)
    const int ty = tid >> 4;      // 0..15 (rows)

    // loader indices
    const int arow = tid >> 2;          // 0..63
    const int acol = (tid & 3) << 2;    // 0,4,8,12
    const int brow = tid >> 5;          // 0..7
    const int bcol = (tid & 31) << 2;   // 0..124

    float acc[8][8];
#pragma unroll
    for (int i = 0; i < 8; ++i)
#pragma unroll
        for (int j = 0; j < 8; ++j) acc[i][j] = 0.0f;

    for (int s = 0; s < d.nseg; ++s) {
        const float* __restrict__ A  = d.seg[s].A;
        const float* __restrict__ Bg = d.seg[s].B;
        const int K   = d.seg[s].K;   // lda == K
        const int ldb = d.N;

        for (int kt = 0; kt < K; kt += BK) {
#pragma unroll
            for (int r = 0; r < 2; ++r) {
                float4 v = *(const float4*)&A[(size_t)(bm * BM + arow + r * 64) * K + kt + acol];
                As[acol + 0][arow + r * 64] = v.x;
                As[acol + 1][arow + r * 64] = v.y;
                As[acol + 2][arow + r * 64] = v.z;
                As[acol + 3][arow + r * 64] = v.w;
            }
#pragma unroll
            for (int r = 0; r < 2; ++r) {
                *(float4*)&Bs[brow + r * 8][bcol] =
                    *(const float4*)&Bg[(size_t)(kt + brow + r * 8) * ldb + bn * BN + bcol];
            }
            __syncthreads();

#pragma unroll
            for (int kk = 0; kk < BK; ++kk) {
                float ra[8], rb[8];
                *(float4*)&ra[0] = *(const float4*)&As[kk][ty * 8];
                *(float4*)&ra[4] = *(const float4*)&As[kk][ty * 8 + 4];
                *(float4*)&rb[0] = *(const float4*)&Bs[kk][tx * 8];
                *(float4*)&rb[4] = *(const float4*)&Bs[kk][tx * 8 + 4];
#pragma unroll
                for (int i = 0; i < 8; ++i)
#pragma unroll
                    for (int j = 0; j < 8; ++j)
                        acc[i][j] += ra[i] * rb[j];
            }
            __syncthreads();
        }
    }

    // ---------------- epilogue ----------------
    const int gm0 = bm * BM + ty * 8;
    const int gn0 = bn * BN + tx * 8;
    const int N = d.N;

    if (d.mode == 0) {
#pragma unroll
        for (int i = 0; i < 8; ++i) {
            float* row = d.state_out + (size_t)(gm0 + i) * N + gn0;
#pragma unroll
            for (int j = 0; j < 8; ++j) row[j] = acc[i][j];
        }
    } else {
#pragma unroll
        for (int i = 0; i < 8; ++i) {
            const size_t off = (size_t)(gm0 + i) * N + gn0;
            const float* prow = d.prev + off;
            float* srow = d.state_out + off;
            float* arow_ = d.act_out + off;
            float* erow = d.extra_out ? d.extra_out + off : nullptr;
#pragma unroll
            for (int j = 0; j < 8; ++j) {
                float v = TAU * (acc[i][j] + d.bias[gn0 + j]) + (1.0f - TAU) * prow[j];
                srow[j] = v;
                float a = 1.0f / (1.0f + expf(-v));
                arow_[j] = a;
                if (erow) erow[j] = a;
            }
        }
    }
}

// ---------------- launch ------------------------------------------------------
extern "C" void kernel_launch(void* const* d_in, const int* in_sizes, int n_in,
                              void* d_out, int out_size) {
    const float* inputs = (const float*)d_in[0];   // [B, T, I]
    const float* w_oh   = (const float*)d_in[1];   // [I, H]
    const float* w_hp   = (const float*)d_in[2];   // [H, P]
    const float* w_pp   = (const float*)d_in[3];   // [P, P]
    const float* w_pc   = (const float*)d_in[4];   // [P, C]
    const float* w_cp   = (const float*)d_in[5];   // [C, P]
    const float* bias_h = (const float*)d_in[6];
    const float* bias_p = (const float*)d_in[7];
    const float* bias_c = (const float*)d_in[8];
    float* out = (float*)d_out;                    // [4, B, P]

    float *U, *ah, *ap, *ps, *ac, *cs;
    cudaGetSymbolAddress((void**)&U,  g_U);
    cudaGetSymbolAddress((void**)&ah, g_ah);
    cudaGetSymbolAddress((void**)&ap, g_ap);
    cudaGetSymbolAddress((void**)&ps, g_ps);
    cudaGetSymbolAddress((void**)&ac, g_ac);
    cudaGetSymbolAddress((void**)&cs, g_cs);

    const size_t PSZ = (size_t)BATCH * PDIM;   // 1M
    const size_t CSZ = (size_t)BATCH * CDIM;   // 512K

    // 1) init carry0
    init_kernel<<<(BATCH * PDIM + 255) / 256, 256>>>();

    // 2) batched input GEMM: U[b*T+t, h] = inputs[b,t,:] @ w_oh
    {
        GemmDesc du = {};
        du.seg[0] = { inputs, w_oh, IDIM };
        du.nseg = 1;
        du.N = HDIM;
        du.grid_n = HDIM / BN;                 // 8
        du.state_out = U;
        du.mode = 0;
        const int blocks = (BATCH * TSTEPS / BM) * du.grid_n;   // 96*8 = 768
        gemm_kernel<<<blocks, 256>>>(du, du, blocks);
    }

    // 3) h-scan (produces a_h_t into slots 1..11)
    hscan_kernel<<<(BATCH * HDIM + 255) / 256, 256>>>(bias_h);

    // 4) sequential p/c steps; P and C GEMMs fused into one launch per step
    for (int t = 0; t < TSTEPS; ++t) {
        const int rd = t & 1;
        const int wr = rd ^ 1;

        GemmDesc dp = {};
        dp.seg[0] = { ah + (size_t)t * PSZ, w_hp, HDIM };   // a_h_{t-1}
        dp.seg[1] = { ap + rd * PSZ,        w_pp, PDIM };   // a_p_{t-1}
        dp.seg[2] = { ac + rd * CSZ,        w_cp, CDIM };   // a_c_{t-1}
        dp.nseg = 3;
        dp.N = PDIM;
        dp.grid_n = PDIM / BN;                 // 8
        dp.bias = bias_p;
        dp.prev = ps + rd * PSZ;
        dp.state_out = ps + wr * PSZ;
        dp.act_out = ap + wr * PSZ;
        dp.extra_out = (t >= TSTEPS - 4) ? out + (size_t)(t - (TSTEPS - 4)) * PSZ : nullptr;
        dp.mode = 1;

        GemmDesc dc = {};
        dc.seg[0] = { ap + rd * PSZ, w_pc, PDIM };          // a_p_{t-1}
        dc.nseg = 1;
        dc.N = CDIM;
        dc.grid_n = CDIM / BN;                 // 4
        dc.bias = bias_c;
        dc.prev = cs + rd * CSZ;
        dc.state_out = cs + wr * CSZ;
        dc.act_out = ac + wr * CSZ;
        dc.extra_out = nullptr;
        dc.mode = 1;

        const int nP = (BATCH / BM) * dp.grid_n;  // 64
        const int nC = (BATCH / BM) * dc.grid_n;  // 32
        gemm_kernel<<<nP + nC, 256>>>(dp, dc, nP);
    }
}

// round 3
// speedup vs baseline: 3.1894x; 3.1894x over previous
#include <cuda_runtime.h>
#include <cstdint>
#include <math.h>

#define BATCH 1024
#define TSTEPS 12
#define TAU 0.25f
#define BK 32
#define SAS 36        // smem row stride (floats): bank = 4*row+tig -> conflict-free frags

// ---------------- static scratch ----------------
__device__ __align__(256) float g_U[(size_t)BATCH * TSTEPS * 1024];
__device__ __align__(256) float g_Xr[(size_t)BATCH * TSTEPS * 1024];  // tf32-rounded inputs
__device__ __align__(256) float g_ah[TSTEPS][(size_t)BATCH * 1024];   // slot t = a_h_{t-1}
__device__ __align__(256) float g_apc[2][(size_t)BATCH * 1536];       // [a_p | a_c]
__device__ __align__(256) float g_ps[2][(size_t)BATCH * 1024];
__device__ __align__(256) float g_cs[2][(size_t)BATCH * 512];
__device__ __align__(256) float g_WpT[(size_t)1024 * 2560];           // [n][k: hp|pp|cp]
__device__ __align__(256) float g_WcT[(size_t)512 * 1024];            // w_pc^T
__device__ __align__(256) float g_WohT[(size_t)1024 * 1024];          // w_oh^T

// ---------------- helpers ----------------
__device__ __forceinline__ uint32_t smem_u32(const void* p) {
    uint32_t a;
    asm("{ .reg .u64 t; cvta.to.shared.u64 t, %1; cvt.u32.u64 %0, t; }" : "=r"(a) : "l"(p));
    return a;
}
__device__ __forceinline__ float to_tf32(float x) {
    uint32_t r;
    asm("cvt.rna.tf32.f32 %0, %1;" : "=r"(r) : "f"(x));
    return __uint_as_float(r);
}
#define CP_ASYNC16(dst, src) \
    asm volatile("cp.async.cg.shared.global [%0], [%1], 16;" :: "r"(dst), "l"(src))
#define CP_COMMIT() asm volatile("cp.async.commit_group;" ::: "memory")
#define CP_WAIT(n)  asm volatile("cp.async.wait_group %0;" :: "n"(n) : "memory")

__device__ __forceinline__ void mma_tf32(float* d, const uint32_t* a, const uint32_t* b) {
    asm volatile(
        "mma.sync.aligned.m16n8k8.row.col.f32.tf32.tf32.f32 "
        "{%0,%1,%2,%3}, {%4,%5,%6,%7}, {%8,%9}, {%0,%1,%2,%3};"
        : "+f"(d[0]), "+f"(d[1]), "+f"(d[2]), "+f"(d[3])
        : "r"(a[0]), "r"(a[1]), "r"(a[2]), "r"(a[3]), "r"(b[0]), "r"(b[1]));
}

// ---------------- small kernels ----------------
__global__ void init_kernel() {
    int i = blockIdx.x * blockDim.x + threadIdx.x;
    if (i < BATCH * 1536) g_apc[0][i] = 0.5f;
    if (i < BATCH * 1024) { g_ah[0][i] = 0.5f; g_ps[0][i] = 0.0f; }
    if (i < BATCH * 512)  g_cs[0][i] = 0.0f;
}

// tf32-round the raw input stream (unbiased RNA — mma itself would truncate)
__global__ void round_inputs(const float* __restrict__ src, float* __restrict__ dst, int n4) {
    int i = blockIdx.x * blockDim.x + threadIdx.x;
    if (i >= n4) return;
    float4 v = ((const float4*)src)[i];
    v.x = to_tf32(v.x); v.y = to_tf32(v.y); v.z = to_tf32(v.z); v.w = to_tf32(v.w);
    ((float4*)dst)[i] = v;
}

// transpose [K][N] -> dst [N][ldd] with RNA-tf32 rounding
__global__ void transpose_rn(const float* __restrict__ src, int K, int N, float* dst, int ldd) {
    __shared__ float t[32][33];
    int n0 = blockIdx.x * 32, k0 = blockIdx.y * 32;
    int tx = threadIdx.x, ty = threadIdx.y;  // 32x8
#pragma unroll
    for (int i = 0; i < 4; ++i)
        t[ty + 8 * i][tx] = src[(size_t)(k0 + ty + 8 * i) * N + n0 + tx];
    __syncthreads();
#pragma unroll
    for (int i = 0; i < 4; ++i)
        dst[(size_t)(n0 + ty + 8 * i) * ldd + k0 + tx] = to_tf32(t[tx][ty + 8 * i]);
}

// h-scan: h_t = TAU*(U_t + bias_h) + 0.75*h_{t-1}; a_h_t = sigmoid -> slot t+1
__global__ void hscan_kernel(const float* __restrict__ bias_h) {
    int i = blockIdx.x * blockDim.x + threadIdx.x;
    if (i >= BATCH * 1024) return;
    int b = i >> 10, h = i & 1023;
    float bh = bias_h[h];
    float hh = 0.0f;
    const float* Ub = g_U + (size_t)b * TSTEPS * 1024 + h;
#pragma unroll
    for (int t = 0; t < TSTEPS - 1; ++t) {
        hh = TAU * (Ub[(size_t)t * 1024] + bh) + (1.0f - TAU) * hh;
        g_ah[t + 1][i] = to_tf32(1.0f / (1.0f + expf(-hh)));
    }
}

// ---------------- warp-MMA tf32 GEMM ----------------
struct GDesc {
    const float* A0; int lda0;     // activations, row-major [M][K]
    const float* A1; int lda1;
    int kSplit;                    // BK-chunks in segment 0
    int nk;                        // total BK-chunks
    const float* BT; int ldb;      // weights K-major [N][Ktot]
    int N;                         // output width
    int grid_n;                    // N/128
    const float* bias;
    const float* prev;
    float* state_out;
    float* act_out; int act_ld; int act_col0;
    float* extra_out;
    int mode;                      // 0: raw store, 1: blend + sigmoid
};

__global__ __launch_bounds__(256, 2)
void tc_gemm(GDesc dA, GDesc dB, int nA) {
    GDesc d; int bid;
    if ((int)blockIdx.x < nA) { d = dA; bid = blockIdx.x; }
    else                      { d = dB; bid = blockIdx.x - nA; }
    const int bm = bid / d.grid_n;
    const int bn = bid % d.grid_n;

    extern __shared__ __align__(16) float smem[];
    float* As = smem;                       // [2][128][SAS]
    float* Bs = smem + 2 * 128 * SAS;       // [2][128][SAS]
    const uint32_t sA = smem_u32(As);
    const uint32_t sB = smem_u32(Bs);

    const int tid  = threadIdx.x;
    const int warp = tid >> 5;
    const int lane = tid & 31;
    const int wm = warp >> 2;               // 0..1
    const int wn = warp & 3;                // 0..3
    const int g  = lane >> 2;               // 0..7
    const int tg = lane & 3;                // 0..3

    const size_t arow = (size_t)bm * 128;
    const size_t brow = (size_t)bn * 128;
    const int ldb = d.ldb;

    float acc[4][4][4];
#pragma unroll
    for (int i = 0; i < 4; ++i)
#pragma unroll
        for (int j = 0; j < 4; ++j)
#pragma unroll
            for (int k = 0; k < 4; ++k) acc[i][j][k] = 0.0f;

    const int lrow = tid >> 3;              // 0..31 base rows (x4 iters)
    const int lc4  = (tid & 7) << 2;        // float4 col 0,4,..28

    auto load_stage = [&](int kc, int s) {
        const float* Ab; int lda, kbase;
        if (kc < d.kSplit) { Ab = d.A0; lda = d.lda0; kbase = kc * BK; }
        else               { Ab = d.A1; lda = d.lda1; kbase = (kc - d.kSplit) * BK; }
        const float* Bb = d.BT + (size_t)kc * BK;
#pragma unroll
        for (int i = 0; i < 4; ++i) {
            int row = lrow + 32 * i;
            uint32_t da = sA + (uint32_t)(((s << 7) + row) * SAS + lc4) * 4u;
            CP_ASYNC16(da, Ab + (arow + row) * lda + kbase + lc4);
            uint32_t db = sB + (uint32_t)(((s << 7) + row) * SAS + lc4) * 4u;
            CP_ASYNC16(db, Bb + (brow + row) * (size_t)ldb + lc4);
        }
        CP_COMMIT();
    };

    auto compute_stage = [&](int s) {
        const float* Ast = As + (s << 7) * SAS;
        const float* Bst = Bs + (s << 7) * SAS;
#pragma unroll
        for (int k8 = 0; k8 < BK / 8; ++k8) {
            const int kk = k8 * 8;
            uint32_t af[4][4], bf[4][2];
#pragma unroll
            for (int mt = 0; mt < 4; ++mt) {
                const float* r0 = Ast + (wm * 64 + mt * 16 + g) * SAS + kk;
                const float* r1 = r0 + 8 * SAS;
                af[mt][0] = __float_as_uint(r0[tg]);
                af[mt][1] = __float_as_uint(r1[tg]);
                af[mt][2] = __float_as_uint(r0[tg + 4]);
                af[mt][3] = __float_as_uint(r1[tg + 4]);
            }
#pragma unroll
            for (int nt = 0; nt < 4; ++nt) {
                const float* rn = Bst + (wn * 32 + nt * 8 + g) * SAS + kk;
                bf[nt][0] = __float_as_uint(rn[tg]);
                bf[nt][1] = __float_as_uint(rn[tg + 4]);
            }
#pragma unroll
            for (int mt = 0; mt < 4; ++mt)
#pragma unroll
                for (int nt = 0; nt < 4; ++nt)
                    mma_tf32(acc[mt][nt], af[mt], bf[nt]);
        }
    };

    // 2-stage cp.async pipeline
    load_stage(0, 0);
    const int nk = d.nk;
    for (int kc = 0; kc < nk; ++kc) {
        if (kc + 1 < nk) {
            load_stage(kc + 1, (kc + 1) & 1);
            CP_WAIT(1);
        } else {
            CP_WAIT(0);
        }
        __syncthreads();
        compute_stage(kc & 1);
        __syncthreads();
    }

    // ---------------- epilogue ----------------
    const int N = d.N;
#pragma unroll
    for (int mt = 0; mt < 4; ++mt) {
        const int r0 = bm * 128 + wm * 64 + mt * 16 + g;
#pragma unroll
        for (int nt = 0; nt < 4; ++nt) {
            const int c0 = bn * 128 + wn * 32 + nt * 8 + tg * 2;
            if (d.mode == 0) {
                float* o0 = d.state_out + (size_t)r0 * N + c0;
                float* o1 = o0 + (size_t)8 * N;
                *(float2*)o0 = make_float2(acc[mt][nt][0], acc[mt][nt][1]);
                *(float2*)o1 = make_float2(acc[mt][nt][2], acc[mt][nt][3]);
            } else {
                float2 bv = *(const float2*)(d.bias + c0);
#pragma unroll
                for (int h = 0; h < 2; ++h) {
                    const int r = r0 + 8 * h;
                    const size_t off = (size_t)r * N + c0;
                    float2 pv = *(const float2*)(d.prev + off);
                    float2 v, a;
                    v.x = TAU * (acc[mt][nt][2 * h + 0] + bv.x) + (1.0f - TAU) * pv.x;
                    v.y = TAU * (acc[mt][nt][2 * h + 1] + bv.y) + (1.0f - TAU) * pv.y;
                    a.x = 1.0f / (1.0f + expf(-v.x));
                    a.y = 1.0f / (1.0f + expf(-v.y));
                    *(float2*)(d.state_out + off) = v;
                    float2 ar = make_float2(to_tf32(a.x), to_tf32(a.y));
                    *(float2*)(d.act_out + (size_t)r * d.act_ld + d.act_col0 + c0) = ar;
                    if (d.extra_out) *(float2*)(d.extra_out + off) = a;
                }
            }
        }
    }
}

// ---------------- launch ----------------
extern "C" void kernel_launch(void* const* d_in, const int* in_sizes, int n_in,
                              void* d_out, int out_size) {
    const float* inputs = (const float*)d_in[0];   // [B, T, I]
    const float* w_oh   = (const float*)d_in[1];
    const float* w_hp   = (const float*)d_in[2];
    const float* w_pp   = (const float*)d_in[3];
    const float* w_pc   = (const float*)d_in[4];
    const float* w_cp   = (const float*)d_in[5];
    const float* bias_h = (const float*)d_in[6];
    const float* bias_p = (const float*)d_in[7];
    const float* bias_c = (const float*)d_in[8];
    float* out = (float*)d_out;                    // [4, B, P]

    float *U, *Xr, *ah, *apc, *ps, *cs, *WpT, *WcT, *WohT;
    cudaGetSymbolAddress((void**)&U,    g_U);
    cudaGetSymbolAddress((void**)&Xr,   g_Xr);
    cudaGetSymbolAddress((void**)&ah,   g_ah);
    cudaGetSymbolAddress((void**)&apc,  g_apc);
    cudaGetSymbolAddress((void**)&ps,   g_ps);
    cudaGetSymbolAddress((void**)&cs,   g_cs);
    cudaGetSymbolAddress((void**)&WpT,  g_WpT);
    cudaGetSymbolAddress((void**)&WcT,  g_WcT);
    cudaGetSymbolAddress((void**)&WohT, g_WohT);

    const int SMEM_DYN = 4 * 128 * SAS * 4;   // 73728
    cudaFuncSetAttribute(tc_gemm, cudaFuncAttributeMaxDynamicSharedMemorySize, SMEM_DYN);

    const size_t HSZ = (size_t)BATCH * 1024;
    const size_t PSZ = (size_t)BATCH * 1024;
    const size_t CSZ = (size_t)BATCH * 512;
    const size_t APCSZ = (size_t)BATCH * 1536;

    init_kernel<<<(BATCH * 1536 + 255) / 256, 256>>>();
    {
        int n4 = BATCH * TSTEPS * 1024 / 4;
        round_inputs<<<(n4 + 255) / 256, 256>>>(inputs, Xr, n4);
        dim3 thr(32, 8);
        transpose_rn<<<dim3(32, 32), thr>>>(w_oh, 1024, 1024, WohT, 1024);
        transpose_rn<<<dim3(32, 32), thr>>>(w_hp, 1024, 1024, WpT + 0,    2560);
        transpose_rn<<<dim3(32, 32), thr>>>(w_pp, 1024, 1024, WpT + 1024, 2560);
        transpose_rn<<<dim3(32, 16), thr>>>(w_cp,  512, 1024, WpT + 2048, 2560);
        transpose_rn<<<dim3(16, 32), thr>>>(w_pc, 1024,  512, WcT, 1024);
    }

    // 1) batched input GEMM: U = Xr @ w_oh  (M = B*T = 12288)
    {
        GDesc du = {};
        du.A0 = Xr; du.lda0 = 1024;
        du.A1 = Xr; du.lda1 = 1024;
        du.kSplit = 1024 / BK; du.nk = 1024 / BK;
        du.BT = WohT; du.ldb = 1024;
        du.N = 1024; du.grid_n = 8;
        du.state_out = U; du.mode = 0;
        const int blocks = (BATCH * TSTEPS / 128) * 8;   // 768
        tc_gemm<<<blocks, 256, SMEM_DYN>>>(du, du, blocks);
    }

    // 2) h-scan
    hscan_kernel<<<(BATCH * 1024 + 255) / 256, 256>>>(bias_h);

    // 3) sequential p/c steps (P + C fused in one launch)
    for (int t = 0; t < TSTEPS; ++t) {
        const int rd = t & 1;
        const int wr = rd ^ 1;

        GDesc dp = {};
        dp.A0 = ah + (size_t)t * HSZ; dp.lda0 = 1024;
        dp.A1 = apc + (size_t)rd * APCSZ; dp.lda1 = 1536;
        dp.kSplit = 1024 / BK; dp.nk = 2560 / BK;
        dp.BT = WpT; dp.ldb = 2560;
        dp.N = 1024; dp.grid_n = 8;
        dp.bias = bias_p;
        dp.prev = ps + (size_t)rd * PSZ;
        dp.state_out = ps + (size_t)wr * PSZ;
        dp.act_out = apc + (size_t)wr * APCSZ; dp.act_ld = 1536; dp.act_col0 = 0;
        dp.extra_out = (t >= TSTEPS - 4) ? out + (size_t)(t - (TSTEPS - 4)) * PSZ : nullptr;
        dp.mode = 1;

        GDesc dc = {};
        dc.A0 = apc + (size_t)rd * APCSZ; dc.lda0 = 1536;
        dc.A1 = dc.A0; dc.lda1 = 1536;
        dc.kSplit = 1024 / BK; dc.nk = 1024 / BK;
        dc.BT = WcT; dc.ldb = 1024;
        dc.N = 512; dc.grid_n = 4;
        dc.bias = bias_c;
        dc.prev = cs + (size_t)rd * CSZ;
        dc.state_out = cs + (size_t)wr * CSZ;
        dc.act_out = apc + (size_t)wr * APCSZ; dc.act_ld = 1536; dc.act_col0 = 1024;
        dc.extra_out = nullptr;
        dc.mode = 1;

        const int nP = (BATCH / 128) * 8;  // 64
        const int nC = (BATCH / 128) * 4;  // 32
        tc_gemm<<<nP + nC, 256, SMEM_DYN>>>(dp, dc, nP);
    }
}

// round 4
// speedup vs baseline: 5.9845x; 1.8764x over previous
#include <cuda_runtime.h>
#include <cuda_fp16.h>
#include <cstdint>
#include <math.h>

#define BATCH 1024
#define TSTEPS 12
#define TAU 0.25f
#define BK 64                 // K halfs per pipeline chunk
#define SROW 72               // smem row stride in halfs (144B) — conflict-free
#define STAGE_BYTES (128 * SROW * 2)

// ---------------- static scratch ----------------
__device__ __align__(256) float  g_U[(size_t)BATCH * TSTEPS * 1024];
__device__ __align__(256) __half g_Xh[(size_t)BATCH * TSTEPS * 1024];
__device__ __align__(256) __half g_ah[TSTEPS][(size_t)BATCH * 1024];   // slot t = a_h_{t-1}
__device__ __align__(256) __half g_apc[2][(size_t)BATCH * 1536];       // [a_p | a_c]
__device__ __align__(256) float  g_psc[2][(size_t)BATCH * 1536];       // [p | c] states
__device__ __align__(256) __half g_Wp[(size_t)1536 * 2560];            // combined Bt [n][k]
__device__ __align__(256) __half g_Woh[(size_t)1024 * 1024];           // w_oh^T
__device__ __align__(256) float  g_biaspc[1536];

// ---------------- helpers ----------------
__device__ __forceinline__ uint32_t smem_u32(const void* p) {
    uint32_t a;
    asm("{ .reg .u64 t; cvta.to.shared.u64 t, %1; cvt.u32.u64 %0, t; }" : "=r"(a) : "l"(p));
    return a;
}
#define CP_ASYNC16(dst, src) \
    asm volatile("cp.async.cg.shared.global [%0], [%1], 16;" :: "r"(dst), "l"(src))
#define CP_COMMIT() asm volatile("cp.async.commit_group;" ::: "memory")
#define CP_WAIT(n)  asm volatile("cp.async.wait_group %0;" :: "n"(n) : "memory")

#define LDSM_X4(r0, r1, r2, r3, a) \
    asm volatile("ldmatrix.sync.aligned.m8n8.x4.shared.b16 {%0,%1,%2,%3}, [%4];" \
                 : "=r"(r0), "=r"(r1), "=r"(r2), "=r"(r3) : "r"(a))

__device__ __forceinline__ void mma_f16(float* d, const uint32_t* a, const uint32_t* b) {
    asm volatile(
        "mma.sync.aligned.m16n8k16.row.col.f32.f16.f16.f32 "
        "{%0,%1,%2,%3}, {%4,%5,%6,%7}, {%8,%9}, {%0,%1,%2,%3};"
        : "+f"(d[0]), "+f"(d[1]), "+f"(d[2]), "+f"(d[3])
        : "r"(a[0]), "r"(a[1]), "r"(a[2]), "r"(a[3]), "r"(b[0]), "r"(b[1]));
}

// ---------------- prep kernels ----------------
__global__ void init_kernel(const float* __restrict__ bias_p, const float* __restrict__ bias_c) {
    int i = blockIdx.x * blockDim.x + threadIdx.x;
    if (i < BATCH * 1536) { g_apc[0][i] = __float2half_rn(0.5f); g_psc[0][i] = 0.0f; }
    if (i < BATCH * 1024) g_ah[0][i] = __float2half_rn(0.5f);
    if (i < 1536) g_biaspc[i] = (i < 1024) ? bias_p[i] : bias_c[i - 1024];
}

// zero rows 1024..1535 of g_Wp (c outputs) before w_pc lands in the middle K-segment
__global__ void zero_wc() {
    size_t i = (size_t)blockIdx.x * blockDim.x + threadIdx.x;   // over 512*2560/8
    if (i < (size_t)512 * 2560 / 8) {
        ((uint4*)(g_Wp + (size_t)1024 * 2560))[i] = make_uint4(0, 0, 0, 0);
    }
}

// fp32 -> fp16 input stream
__global__ void conv_inputs(const float* __restrict__ src, int n8) {
    int i = blockIdx.x * blockDim.x + threadIdx.x;
    if (i >= n8) return;
    float4 a = ((const float4*)src)[2 * i];
    float4 b = ((const float4*)src)[2 * i + 1];
    __half2 h0 = __floats2half2_rn(a.x, a.y);
    __half2 h1 = __floats2half2_rn(a.z, a.w);
    __half2 h2 = __floats2half2_rn(b.x, b.y);
    __half2 h3 = __floats2half2_rn(b.z, b.w);
    uint4 o;
    o.x = *(uint32_t*)&h0; o.y = *(uint32_t*)&h1;
    o.z = *(uint32_t*)&h2; o.w = *(uint32_t*)&h3;
    ((uint4*)g_Xh)[i] = o;
}

// transpose fp32 [K][N] -> fp16 dst[N][ldd], column offset koff
__global__ void transpose_h(const float* __restrict__ src, int K, int N,
                            __half* __restrict__ dst, int ldd, int koff) {
    __shared__ float t[32][33];
    int n0 = blockIdx.x * 32, k0 = blockIdx.y * 32;
    int tx = threadIdx.x, ty = threadIdx.y;  // 32x8
#pragma unroll
    for (int i = 0; i < 4; ++i)
        t[ty + 8 * i][tx] = src[(size_t)(k0 + ty + 8 * i) * N + n0 + tx];
    __syncthreads();
#pragma unroll
    for (int i = 0; i < 4; ++i)
        dst[(size_t)(n0 + ty + 8 * i) * ldd + koff + k0 + tx] = __float2half_rn(t[tx][ty + 8 * i]);
}

// h-scan: h_t = TAU*(U_t + bias_h) + 0.75*h_{t-1}; a_h_t -> slot t+1 (fp16)
__global__ void hscan_kernel(const float* __restrict__ bias_h) {
    int i = blockIdx.x * blockDim.x + threadIdx.x;
    if (i >= BATCH * 1024) return;
    int b = i >> 10, h = i & 1023;
    float bh = bias_h[h];
    float hh = 0.0f;
    const float* Ub = g_U + (size_t)b * TSTEPS * 1024 + h;
#pragma unroll
    for (int t = 0; t < TSTEPS - 1; ++t) {
        hh = TAU * (Ub[(size_t)t * 1024] + bh) + (1.0f - TAU) * hh;
        g_ah[t + 1][i] = __float2half_rn(1.0f / (1.0f + expf(-hh)));
    }
}

// ---------------- fp16 warp-MMA GEMM ----------------
struct GDesc {
    const __half* A0; int lda0;    // activations row-major [M][K] (halfs)
    const __half* A1; int lda1;
    int kSplit;                    // BK-chunks in segment 0
    int nk;                        // total BK-chunks
    const __half* BT; int ldb;     // weights [N][Ktot]
    int N;                         // output width / ld of state, prev, act
    int grid_n;
    const float* bias;
    const float* prev;
    float* state_out;              // fp32
    __half* act_out;               // fp16 (mode 1)
    float* extra_out;              // d_out slice (cols < 1024 only)
    int mode;                      // 0 raw store, 1 blend+sigmoid
};

__global__ __launch_bounds__(256, 2)
void tc_gemm(GDesc d) {
    const int bid = blockIdx.x;
    const int bm = bid / d.grid_n;
    const int bn = bid % d.grid_n;

    extern __shared__ __align__(16) __half smem[];
    __half* As = smem;                          // [2][128][SROW]
    __half* Bs = smem + 2 * 128 * SROW;
    const uint32_t sA = smem_u32(As);
    const uint32_t sB = smem_u32(Bs);

    const int tid  = threadIdx.x;
    const int warp = tid >> 5;
    const int lane = tid & 31;
    const int wm = warp >> 2;               // 0..1
    const int wn = warp & 3;                // 0..3
    const int g  = lane >> 2;
    const int tg = lane & 3;

    const size_t arow = (size_t)bm * 128;
    const size_t brow = (size_t)bn * 128;
    const int ldb = d.ldb;

    float acc[4][4][4];
#pragma unroll
    for (int i = 0; i < 4; ++i)
#pragma unroll
        for (int j = 0; j < 4; ++j)
#pragma unroll
            for (int k = 0; k < 4; ++k) acc[i][j][k] = 0.0f;

    // cp.async mapping: 128 rows x 8 chunks(16B) per tile, 4 rows/thread
    const int lrow = tid >> 3;              // 0..31 (+32*i)
    const int lch  = (tid & 7) << 3;        // half col: 0,8,..56

    auto load_stage = [&](int kc, int s) {
        const __half* Ab; int lda, kbase;
        if (kc < d.kSplit) { Ab = d.A0; lda = d.lda0; kbase = kc * BK; }
        else               { Ab = d.A1; lda = d.lda1; kbase = (kc - d.kSplit) * BK; }
        const __half* Bb = d.BT + (size_t)kc * BK;
        const uint32_t so = s * STAGE_BYTES;
#pragma unroll
        for (int i = 0; i < 4; ++i) {
            int row = lrow + 32 * i;
            CP_ASYNC16(sA + so + (uint32_t)(row * SROW + lch) * 2u,
                       Ab + (arow + row) * lda + kbase + lch);
            CP_ASYNC16(sB + so + (uint32_t)(row * SROW + lch) * 2u,
                       Bb + (brow + row) * (size_t)ldb + lch);
        }
        CP_COMMIT();
    };

    // ldmatrix lane bases
    const uint32_t aLane =
        (uint32_t)(((wm * 64) + (((lane >> 3) & 1) << 3) + (lane & 7)) * SROW +
                   ((lane >> 4) << 3)) * 2u;
    const uint32_t bLane =
        (uint32_t)(((wn * 32) + (((lane >> 4) & 1) << 3) + (lane & 7)) * SROW +
                   (((lane >> 3) & 1) << 3)) * 2u;

    auto compute_stage = [&](int s) {
        const uint32_t aOff = sA + s * STAGE_BYTES + aLane;
        const uint32_t bOff = sB + s * STAGE_BYTES + bLane;
#pragma unroll
        for (int k16 = 0; k16 < BK / 16; ++k16) {
            uint32_t af[4][4], bf[2][4];
#pragma unroll
            for (int mt = 0; mt < 4; ++mt)
                LDSM_X4(af[mt][0], af[mt][1], af[mt][2], af[mt][3],
                        aOff + mt * 16 * SROW * 2 + k16 * 32);
#pragma unroll
            for (int np = 0; np < 2; ++np)
                LDSM_X4(bf[np][0], bf[np][1], bf[np][2], bf[np][3],
                        bOff + np * 16 * SROW * 2 + k16 * 32);
#pragma unroll
            for (int mt = 0; mt < 4; ++mt)
#pragma unroll
                for (int nt = 0; nt < 4; ++nt)
                    mma_f16(acc[mt][nt], af[mt], &bf[nt >> 1][(nt & 1) * 2]);
        }
    };

    load_stage(0, 0);
    const int nk = d.nk;
    for (int kc = 0; kc < nk; ++kc) {
        if (kc + 1 < nk) {
            load_stage(kc + 1, (kc + 1) & 1);
            CP_WAIT(1);
        } else {
            CP_WAIT(0);
        }
        __syncthreads();
        compute_stage(kc & 1);
        __syncthreads();
    }

    // ---------------- epilogue ----------------
    const int N = d.N;
    const bool isP = (bn * 128) < 1024;
#pragma unroll
    for (int mt = 0; mt < 4; ++mt) {
        const int r0 = bm * 128 + wm * 64 + mt * 16 + g;
#pragma unroll
        for (int nt = 0; nt < 4; ++nt) {
            const int c0 = bn * 128 + wn * 32 + nt * 8 + tg * 2;
            if (d.mode == 0) {
                float* o0 = d.state_out + (size_t)r0 * N + c0;
                float* o1 = o0 + (size_t)8 * N;
                *(float2*)o0 = make_float2(acc[mt][nt][0], acc[mt][nt][1]);
                *(float2*)o1 = make_float2(acc[mt][nt][2], acc[mt][nt][3]);
            } else {
                float2 bv = *(const float2*)(d.bias + c0);
#pragma unroll
                for (int h = 0; h < 2; ++h) {
                    const int r = r0 + 8 * h;
                    const size_t off = (size_t)r * N + c0;
                    float2 pv = *(const float2*)(d.prev + off);
                    float2 v, a;
                    v.x = TAU * (acc[mt][nt][2 * h + 0] + bv.x) + (1.0f - TAU) * pv.x;
                    v.y = TAU * (acc[mt][nt][2 * h + 1] + bv.y) + (1.0f - TAU) * pv.y;
                    a.x = 1.0f / (1.0f + expf(-v.x));
                    a.y = 1.0f / (1.0f + expf(-v.y));
                    *(float2*)(d.state_out + off) = v;
                    *(__half2*)(d.act_out + off) = __floats2half2_rn(a.x, a.y);
                    if (d.extra_out && isP)
                        *(float2*)(d.extra_out + (size_t)r * 1024 + c0) = a;
                }
            }
        }
    }
}

// ---------------- launch ----------------
extern "C" void kernel_launch(void* const* d_in, const int* in_sizes, int n_in,
                              void* d_out, int out_size) {
    const float* inputs = (const float*)d_in[0];
    const float* w_oh   = (const float*)d_in[1];
    const float* w_hp   = (const float*)d_in[2];
    const float* w_pp   = (const float*)d_in[3];
    const float* w_pc   = (const float*)d_in[4];
    const float* w_cp   = (const float*)d_in[5];
    const float* bias_h = (const float*)d_in[6];
    const float* bias_p = (const float*)d_in[7];
    const float* bias_c = (const float*)d_in[8];
    float* out = (float*)d_out;                    // [4, B, 1024]

    float *U, *psc, *biaspc;
    __half *Xh, *ah, *apc, *Wp, *Woh;
    cudaGetSymbolAddress((void**)&U,     g_U);
    cudaGetSymbolAddress((void**)&Xh,    g_Xh);
    cudaGetSymbolAddress((void**)&ah,    g_ah);
    cudaGetSymbolAddress((void**)&apc,   g_apc);
    cudaGetSymbolAddress((void**)&psc,   g_psc);
    cudaGetSymbolAddress((void**)&Wp,    g_Wp);
    cudaGetSymbolAddress((void**)&Woh,   g_Woh);
    cudaGetSymbolAddress((void**)&biaspc, g_biaspc);

    const int SMEM_DYN = 2 * STAGE_BYTES * 2;   // 73728
    cudaFuncSetAttribute(tc_gemm, cudaFuncAttributeMaxDynamicSharedMemorySize, SMEM_DYN);

    const size_t HSZ = (size_t)BATCH * 1024;
    const size_t PCSZ = (size_t)BATCH * 1536;

    // 0) prep
    init_kernel<<<(BATCH * 1536 + 255) / 256, 256>>>(bias_p, bias_c);
    zero_wc<<<((512 * 2560 / 8) + 255) / 256, 256>>>();
    {
        int n8 = BATCH * TSTEPS * 1024 / 8;
        conv_inputs<<<(n8 + 255) / 256, 256>>>(inputs, n8);
        dim3 thr(32, 8);
        transpose_h<<<dim3(32, 32), thr>>>(w_oh, 1024, 1024, Woh, 1024, 0);
        // combined B rows 0..1023 (p outputs): [w_hp^T | w_pp^T | w_cp^T]
        transpose_h<<<dim3(32, 32), thr>>>(w_hp, 1024, 1024, Wp, 2560, 0);
        transpose_h<<<dim3(32, 32), thr>>>(w_pp, 1024, 1024, Wp, 2560, 1024);
        transpose_h<<<dim3(32, 16), thr>>>(w_cp,  512, 1024, Wp, 2560, 2048);
        // rows 1024..1535 (c outputs): w_pc^T in K-segment [1024,2048), zeros elsewhere
        transpose_h<<<dim3(16, 32), thr>>>(w_pc, 1024,  512, Wp + (size_t)1024 * 2560, 2560, 1024);
    }

    // 1) batched input GEMM: U = Xh @ w_oh  (M = 12288)
    {
        GDesc du = {};
        du.A0 = Xh; du.lda0 = 1024;
        du.A1 = Xh; du.lda1 = 1024;
        du.kSplit = 1024 / BK; du.nk = 1024 / BK;
        du.BT = Woh; du.ldb = 1024;
        du.N = 1024; du.grid_n = 8;
        du.state_out = U; du.mode = 0;
        tc_gemm<<<(BATCH * TSTEPS / 128) * 8, 256, SMEM_DYN>>>(du);
    }

    // 2) h-scan
    hscan_kernel<<<(BATCH * 1024 + 255) / 256, 256>>>(bias_h);

    // 3) sequential combined [p|c] steps — one uniform GEMM per step
    for (int t = 0; t < TSTEPS; ++t) {
        const int rd = t & 1;
        const int wr = rd ^ 1;

        GDesc ds = {};
        ds.A0 = ah + (size_t)t * HSZ; ds.lda0 = 1024;      // a_h_{t-1}
        ds.A1 = apc + (size_t)rd * PCSZ; ds.lda1 = 1536;   // [a_p | a_c]_{t-1}
        ds.kSplit = 1024 / BK; ds.nk = 2560 / BK;
        ds.BT = Wp; ds.ldb = 2560;
        ds.N = 1536; ds.grid_n = 12;
        ds.bias = biaspc;
        ds.prev = psc + (size_t)rd * PCSZ;
        ds.state_out = psc + (size_t)wr * PCSZ;
        ds.act_out = apc + (size_t)wr * PCSZ;
        ds.extra_out = (t >= TSTEPS - 4) ? out + (size_t)(t - (TSTEPS - 4)) * BATCH * 1024 : nullptr;
        ds.mode = 1;

        tc_gemm<<<8 * 12, 256, SMEM_DYN>>>(ds);    // 96 equal CTAs
    }
}